// round 5
// baseline (speedup 1.0000x reference)
#include <cuda_runtime.h>

// DistMaps: out[b,g,r,c] = tanh(2*sqrt(min_p d2)) over 24 clicks per (b,g) group,
// d2 = ((r-pr)/5)^2 + ((c-pc)/5)^2, invalid clicks (max coords < 0) -> 1e6.
// x input (d_in[0]) is shape-only; output depends only on coords (d_in[1]).
//
// R5: fill + patch, but patch exposes full parallelism: each 68x72 patch is
// split over 5 blocks (grid 24 x 16 x 5 = 1920 blocks), ONE quad per thread,
// no loops over pixels. R4's patch kernel was latency-bound (384 blocks,
// 4.8 serial quad iterations/thread, occ 28.8%, issue 40.9%).
//
// Pixels farther than sqrt(41)*5 = 32.03 px from every valid click give
// tanh(>=12.8) == 1.0f exactly, so the background fill of 1.0f is exact.
// Box-culled click set contains every click within reach of ANY box pixel,
// so every patch block computes the exact clamped min; overlapping patches
// write identical values -> benign duplicate writes.

namespace {

constexpr int   H         = 512;
constexpr int   W         = 512;
constexpr int   P         = 24;      // clicks per group
constexpr float INV_SCALE = 0.2f;    // 1 / (NORM_RADIUS * SPATIAL_SCALE)
constexpr float CULL_D2   = 41.0f;   // d2 >= 41 -> tanh rounds to exactly 1.0f

constexpr int PROWS  = 68;           // patch rows  (radius 32.03 + slack)
constexpr int PCOLS  = 72;           // patch cols  (float4-aligned)
constexpr int PQ     = PCOLS / 4;    // 18 quads per patch row
constexpr int PQUADS = PROWS * PQ;   // 1224
constexpr int PSPLIT = (PQUADS + 255) / 256;  // 5 blocks per patch

__device__ __forceinline__ float tanh_2sqrt_fast(float q) {
    float s, t;
    asm("sqrt.approx.f32 %0, %1;" : "=f"(s) : "f"(q));
    s = 2.0f * s;
    asm("tanh.approx.f32 %0, %1;" : "=f"(t) : "f"(s));
    return t;
}

__global__ __launch_bounds__(256) void fill_kernel(float4* __restrict__ out) {
    const int i = blockIdx.x * 256 + threadIdx.x;
    out[i] = make_float4(1.0f, 1.0f, 1.0f, 1.0f);
}

__global__ __launch_bounds__(256) void patch_kernel(
    const float* __restrict__ coords,   // [B, 48, 3] (row, col, _)
    float*       __restrict__ out)      // [B, 2, H, W]
{
    __shared__ float s_prs[P];
    __shared__ float s_pcs[P];
    __shared__ int   s_n;

    const int pk  = blockIdx.x;      // click index within group, 0..23
    const int bg  = blockIdx.y;      // 0..2B-1
    const int tid = threadIdx.x;

    // Center click of this patch (uniform broadcast load).
    const float* cp = coords + (size_t)(bg * P + pk) * 3;
    const float pr = __ldg(cp);
    const float pc = __ldg(cp + 1);
    if (fmaxf(pr, pc) < 0.0f) return;   // invalid click: fill value stands

    // Patch box (clamped to image, column base float4-aligned).
    int row_lo = (int)floorf(pr) - 33;
    row_lo = max(0, min(row_lo, H - PROWS));
    int col_lo = ((int)floorf(pc) - 34) & ~3;
    col_lo = max(0, min(col_lo, W - PCOLS));

    // Warp 0: keep clicks whose scaled rect-distance^2 to the box is < 41.
    if (tid < 32) {
        bool  near = false;
        float prs = 0.0f, pcs = 0.0f;
        if (tid < P) {
            const float* cq = coords + (size_t)(bg * P + tid) * 3;
            float qr = cq[0];
            float qc = cq[1];
            bool valid = fmaxf(qr, qc) >= 0.0f;
            float rr = fminf(fmaxf(qr, (float)row_lo), (float)(row_lo + PROWS - 1));
            float cc = fminf(fmaxf(qc, (float)col_lo), (float)(col_lo + PCOLS - 1));
            float dr = (rr - qr) * INV_SCALE;
            float dc = (cc - qc) * INV_SCALE;
            near = valid && (fmaf(dr, dr, dc * dc) < CULL_D2);
            prs = qr * INV_SCALE;
            pcs = qc * INV_SCALE;
        }
        unsigned mask = __ballot_sync(0xffffffffu, near);
        if (near) {
            int pos = __popc(mask & ((1u << tid) - 1u));
            s_prs[pos] = prs;
            s_pcs[pos] = pcs;
        }
        if (tid == 0) s_n = __popc(mask);
    }
    __syncthreads();

    // One quad per thread.
    const int qi = blockIdx.z * 256 + tid;
    if (qi >= PQUADS) return;

    const int n = s_n;   // >= 1 (the center click always survives)

    const int r   = qi / PQ;          // const divisor -> mul/shift
    const int c4  = qi - r * PQ;
    const int row = row_lo + r;
    const int col = col_lo + c4 * 4;

    const float rs = (float)row * INV_SCALE;
    const float a0 = (float)(col + 0) * INV_SCALE;
    const float a1 = (float)(col + 1) * INV_SCALE;
    const float a2 = (float)(col + 2) * INV_SCALE;
    const float a3 = (float)(col + 3) * INV_SCALE;

    float q0 = CULL_D2, q1 = CULL_D2, q2 = CULL_D2, q3 = CULL_D2;

    for (int p = 0; p < n; ++p) {
        const float dr  = rs - s_prs[p];
        const float e   = dr * dr;
        const float pcs = s_pcs[p];
        float d;
        d = a0 - pcs; q0 = fminf(q0, fmaf(d, d, e));
        d = a1 - pcs; q1 = fminf(q1, fmaf(d, d, e));
        d = a2 - pcs; q2 = fminf(q2, fmaf(d, d, e));
        d = a3 - pcs; q3 = fminf(q3, fmaf(d, d, e));
    }

    float4 v;
    v.x = tanh_2sqrt_fast(q0);
    v.y = tanh_2sqrt_fast(q1);
    v.z = tanh_2sqrt_fast(q2);
    v.w = tanh_2sqrt_fast(q3);
    *reinterpret_cast<float4*>(out + ((size_t)bg * H + row) * W + col) = v;
}

}  // namespace

extern "C" void kernel_launch(void* const* d_in, const int* in_sizes, int n_in,
                              void* d_out, int out_size) {
    // d_in[0]: x [B,3,512,512] f32 (unused), d_in[1]: coords [B,48,3] f32
    const float* coords = (const float*)d_in[1];
    float* out = (float*)d_out;

    const int B  = in_sizes[1] / (48 * 3);   // 8
    const int n4 = out_size / 4;             // 1,048,576 quads

    fill_kernel<<<n4 / 256, 256>>>(reinterpret_cast<float4*>(out));

    dim3 grid(P, B * 2, PSPLIT);
    patch_kernel<<<grid, 256>>>(coords, out);
}

// round 6
// speedup vs baseline: 1.2007x; 1.2007x over previous
#include <cuda_runtime.h>

// DistMaps: out[b,g,r,c] = tanh(2*sqrt(min_p d2)) over 24 clicks per (b,g) group,
// d2 = ((r-pr)/5)^2 + ((c-pc)/5)^2, invalid clicks (max coords < 0) -> 1e6.
// x input (d_in[0]) is shape-only; output depends only on coords (d_in[1]).
//
// R6: single kernel, warp-granular everything. Each warp owns a 4-row x 128-col
// window. Lane p (<24) loads click p and tests its rect-distance to the window;
// one ballot gives the warp's survivor mask (avg ~1.1 clicks, 34% of warps get
// zero -> pure ones stores). No shared memory, no __syncthreads, no block cull:
// R4/R5 showed per-block prologue + LDS-stall overhead dominated, invariant to
// block restructuring.
//
// d2 >= 41 => 2*sqrt(d2) >= 12.8 => tanh rounds to exactly 1.0f, so clamping
// the min at 41 and writing 1.0f for unreached pixels is exact.

namespace {

constexpr int   H         = 512;
constexpr int   W         = 512;
constexpr int   P         = 24;      // clicks per group
constexpr float INV_SCALE = 0.2f;    // 1 / (NORM_RADIUS * SPATIAL_SCALE)
constexpr float CULL_D2   = 41.0f;

__device__ __forceinline__ float tanh_2sqrt_fast(float q) {
    float s, t;
    asm("sqrt.approx.f32 %0, %1;" : "=f"(s) : "f"(q));
    s = 2.0f * s;
    asm("tanh.approx.f32 %0, %1;" : "=f"(t) : "f"(s));
    return t;
}

__global__ __launch_bounds__(256) void distmaps_kernel(
    const float* __restrict__ coords,   // [B, 48, 3] (row, col, _)
    float*       __restrict__ out)      // [B, 2, H, W]
{
    const int tid  = threadIdx.x;
    const int wid  = tid >> 5;
    const int lane = tid & 31;
    const int bg   = blockIdx.y;                 // 0..2B-1

    const int wloc = blockIdx.x * 8 + wid;       // 0..511 warp slot within group
    const int r0   = (wloc >> 2) << 2;           // warp row base (4 rows)
    const int c0   = (wloc & 3)  << 7;           // warp col base (128 cols)

    // Lane p holds click p; test click against this warp's 4x128 window.
    float prs = 0.0f, pcs = 0.0f;
    bool  near = false;
    if (lane < P) {
        const float* cp = coords + (size_t)(bg * P + lane) * 3;
        const float pr = __ldg(cp);
        const float pc = __ldg(cp + 1);
        const bool valid = fmaxf(pr, pc) >= 0.0f;    // invalid iff both < 0
        const float rr = fminf(fmaxf(pr, (float)r0), (float)(r0 + 3));
        const float cc = fminf(fmaxf(pc, (float)c0), (float)(c0 + 127));
        const float dr = (rr - pr) * INV_SCALE;
        const float dc = (cc - pc) * INV_SCALE;
        near = valid && (fmaf(dr, dr, dc * dc) < CULL_D2);
        prs = pr * INV_SCALE;
        pcs = pc * INV_SCALE;
    }
    unsigned mask = __ballot_sync(0xffffffffu, near);

    const int colq = c0 + lane * 4;              // this thread's 4 columns
    float* obase = out + ((size_t)bg * H + r0) * W + colq;

    if (mask == 0u) {
        // No click reaches this window: every pixel is exactly 1.0f.
        const float4 ones = make_float4(1.0f, 1.0f, 1.0f, 1.0f);
#pragma unroll
        for (int i = 0; i < 4; ++i)
            *reinterpret_cast<float4*>(obase + (size_t)i * W) = ones;
        return;
    }

    const float a0 = (float)(colq + 0) * INV_SCALE;
    const float a1 = (float)(colq + 1) * INV_SCALE;
    const float a2 = (float)(colq + 2) * INV_SCALE;
    const float a3 = (float)(colq + 3) * INV_SCALE;
    const float rs0 = (float)(r0 + 0) * INV_SCALE;
    const float rs1 = (float)(r0 + 1) * INV_SCALE;
    const float rs2 = (float)(r0 + 2) * INV_SCALE;
    const float rs3 = (float)(r0 + 3) * INV_SCALE;

    float q[4][4];
#pragma unroll
    for (int i = 0; i < 4; ++i)
#pragma unroll
        for (int j = 0; j < 4; ++j) q[i][j] = CULL_D2;

    // Iterate surviving clicks (warp-uniform mask -> no divergence).
    while (mask) {
        const int p = __ffs(mask) - 1;
        mask &= mask - 1;
        const float pr = __shfl_sync(0xffffffffu, prs, p);
        const float pc = __shfl_sync(0xffffffffu, pcs, p);

        const float dc0 = a0 - pc, dc1 = a1 - pc, dc2 = a2 - pc, dc3 = a3 - pc;
        float dr, e;
        dr = rs0 - pr; e = dr * dr;
        q[0][0] = fminf(q[0][0], fmaf(dc0, dc0, e));
        q[0][1] = fminf(q[0][1], fmaf(dc1, dc1, e));
        q[0][2] = fminf(q[0][2], fmaf(dc2, dc2, e));
        q[0][3] = fminf(q[0][3], fmaf(dc3, dc3, e));
        dr = rs1 - pr; e = dr * dr;
        q[1][0] = fminf(q[1][0], fmaf(dc0, dc0, e));
        q[1][1] = fminf(q[1][1], fmaf(dc1, dc1, e));
        q[1][2] = fminf(q[1][2], fmaf(dc2, dc2, e));
        q[1][3] = fminf(q[1][3], fmaf(dc3, dc3, e));
        dr = rs2 - pr; e = dr * dr;
        q[2][0] = fminf(q[2][0], fmaf(dc0, dc0, e));
        q[2][1] = fminf(q[2][1], fmaf(dc1, dc1, e));
        q[2][2] = fminf(q[2][2], fmaf(dc2, dc2, e));
        q[2][3] = fminf(q[2][3], fmaf(dc3, dc3, e));
        dr = rs3 - pr; e = dr * dr;
        q[3][0] = fminf(q[3][0], fmaf(dc0, dc0, e));
        q[3][1] = fminf(q[3][1], fmaf(dc1, dc1, e));
        q[3][2] = fminf(q[3][2], fmaf(dc2, dc2, e));
        q[3][3] = fminf(q[3][3], fmaf(dc3, dc3, e));
    }

    // Per-row epilogue with warp vote to skip MUFU on fully saturated rows.
#pragma unroll
    for (int i = 0; i < 4; ++i) {
        const float rmin = fminf(fminf(q[i][0], q[i][1]), fminf(q[i][2], q[i][3]));
        float4 v;
        if (__all_sync(0xffffffffu, rmin >= CULL_D2)) {
            v = make_float4(1.0f, 1.0f, 1.0f, 1.0f);
        } else {
            v.x = tanh_2sqrt_fast(q[i][0]);
            v.y = tanh_2sqrt_fast(q[i][1]);
            v.z = tanh_2sqrt_fast(q[i][2]);
            v.w = tanh_2sqrt_fast(q[i][3]);
        }
        *reinterpret_cast<float4*>(obase + (size_t)i * W) = v;
    }
}

}  // namespace

extern "C" void kernel_launch(void* const* d_in, const int* in_sizes, int n_in,
                              void* d_out, int out_size) {
    // d_in[0]: x [B,3,512,512] f32 (unused), d_in[1]: coords [B,48,3] f32
    const float* coords = (const float*)d_in[1];
    float* out = (float*)d_out;

    const int B = in_sizes[1] / (48 * 3);   // 8
    dim3 grid(64, B * 2);                   // 64 blocks x 16 groups, 8 warps each
    distmaps_kernel<<<grid, 256>>>(coords, out);
}

// round 7
// speedup vs baseline: 1.2316x; 1.0257x over previous
#include <cuda_runtime.h>

// DistMaps: out[b,g,r,c] = tanh(2*sqrt(min_p d2)) over 24 clicks per (b,g) group,
// d2 = ((r-pr)/5)^2 + ((c-pc)/5)^2, invalid clicks (max coords < 0) -> 1e6.
// x input (d_in[0]) is shape-only; output depends only on coords (d_in[1]).
//
// R7: cost tracks WARP COUNT, not pixels (R4-R6 invariance, all pipes <25%).
// So: 8-row x 128-col window per warp (32 px/thread), halving warps to 4096
// and amortizing the fixed prologue (coords load+cull+ballot+index math) 2x.
// Same warp-granular cull: lane p tests click p against the window, one ballot.
//
// d2 >= 41 => 2*sqrt(d2) >= 12.8 => tanh rounds to exactly 1.0f, so clamping
// the min at 41 and writing 1.0f for unreached pixels is exact.

namespace {

constexpr int   H         = 512;
constexpr int   W         = 512;
constexpr int   P         = 24;      // clicks per group
constexpr int   WR        = 8;       // rows per warp window
constexpr float INV_SCALE = 0.2f;    // 1 / (NORM_RADIUS * SPATIAL_SCALE)
constexpr float CULL_D2   = 41.0f;

__device__ __forceinline__ float tanh_2sqrt_fast(float q) {
    float s, t;
    asm("sqrt.approx.f32 %0, %1;" : "=f"(s) : "f"(q));
    s = 2.0f * s;
    asm("tanh.approx.f32 %0, %1;" : "=f"(t) : "f"(s));
    return t;
}

__global__ __launch_bounds__(256) void distmaps_kernel(
    const float* __restrict__ coords,   // [B, 48, 3] (row, col, _)
    float*       __restrict__ out)      // [B, 2, H, W]
{
    const int tid  = threadIdx.x;
    const int wid  = tid >> 5;
    const int lane = tid & 31;
    const int bg   = blockIdx.y;                 // 0..2B-1

    const int wloc = blockIdx.x * 8 + wid;       // 0..255 window slot in group
    const int r0   = (wloc >> 2) * WR;           // window row base (8 rows)
    const int c0   = (wloc & 3)  << 7;           // window col base (128 cols)

    // Lane p holds click p; test click against this warp's 8x128 window.
    float prs = 0.0f, pcs = 0.0f;
    bool  near = false;
    if (lane < P) {
        const float* cp = coords + (size_t)(bg * P + lane) * 3;
        const float pr = __ldg(cp);
        const float pc = __ldg(cp + 1);
        const bool valid = fmaxf(pr, pc) >= 0.0f;    // invalid iff both < 0
        const float rr = fminf(fmaxf(pr, (float)r0), (float)(r0 + WR - 1));
        const float cc = fminf(fmaxf(pc, (float)c0), (float)(c0 + 127));
        const float dr = (rr - pr) * INV_SCALE;
        const float dc = (cc - pc) * INV_SCALE;
        near = valid && (fmaf(dr, dr, dc * dc) < CULL_D2);
        prs = pr * INV_SCALE;
        pcs = pc * INV_SCALE;
    }
    unsigned mask = __ballot_sync(0xffffffffu, near);

    const int colq = c0 + lane * 4;              // this thread's 4 columns
    float* obase = out + ((size_t)bg * H + r0) * W + colq;

    if (mask == 0u) {
        // No click reaches this window: every pixel is exactly 1.0f.
        const float4 ones = make_float4(1.0f, 1.0f, 1.0f, 1.0f);
#pragma unroll
        for (int i = 0; i < WR; ++i)
            *reinterpret_cast<float4*>(obase + (size_t)i * W) = ones;
        return;
    }

    const float a0  = (float)(colq + 0) * INV_SCALE;
    const float a1  = (float)(colq + 1) * INV_SCALE;
    const float a2  = (float)(colq + 2) * INV_SCALE;
    const float a3  = (float)(colq + 3) * INV_SCALE;
    const float rs0 = (float)r0 * INV_SCALE;

    float q[WR][4];
#pragma unroll
    for (int i = 0; i < WR; ++i)
#pragma unroll
        for (int j = 0; j < 4; ++j) q[i][j] = CULL_D2;

    // Iterate surviving clicks (warp-uniform mask -> no divergence).
    while (mask) {
        const int p = __ffs(mask) - 1;
        mask &= mask - 1;
        const float pr = __shfl_sync(0xffffffffu, prs, p);
        const float pc = __shfl_sync(0xffffffffu, pcs, p);

        const float dc0 = a0 - pc, dc1 = a1 - pc, dc2 = a2 - pc, dc3 = a3 - pc;
        const float f0 = dc0 * dc0, f1 = dc1 * dc1, f2 = dc2 * dc2, f3 = dc3 * dc3;
        const float dr0 = rs0 - pr;
#pragma unroll
        for (int i = 0; i < WR; ++i) {
            const float dr = dr0 + (float)i * INV_SCALE;
            const float e  = dr * dr;
            q[i][0] = fminf(q[i][0], e + f0);
            q[i][1] = fminf(q[i][1], e + f1);
            q[i][2] = fminf(q[i][2], e + f2);
            q[i][3] = fminf(q[i][3], e + f3);
        }
    }

    // Per-row epilogue with warp vote to skip MUFU on fully saturated rows.
#pragma unroll
    for (int i = 0; i < WR; ++i) {
        const float rmin = fminf(fminf(q[i][0], q[i][1]), fminf(q[i][2], q[i][3]));
        float4 v;
        if (__all_sync(0xffffffffu, rmin >= CULL_D2)) {
            v = make_float4(1.0f, 1.0f, 1.0f, 1.0f);
        } else {
            v.x = tanh_2sqrt_fast(q[i][0]);
            v.y = tanh_2sqrt_fast(q[i][1]);
            v.z = tanh_2sqrt_fast(q[i][2]);
            v.w = tanh_2sqrt_fast(q[i][3]);
        }
        *reinterpret_cast<float4*>(obase + (size_t)i * W) = v;
    }
}

}  // namespace

extern "C" void kernel_launch(void* const* d_in, const int* in_sizes, int n_in,
                              void* d_out, int out_size) {
    // d_in[0]: x [B,3,512,512] f32 (unused), d_in[1]: coords [B,48,3] f32
    const float* coords = (const float*)d_in[1];
    float* out = (float*)d_out;

    const int B = in_sizes[1] / (48 * 3);   // 8
    dim3 grid(32, B * 2);                   // 32 blocks x 16 groups, 8 warps each
    distmaps_kernel<<<grid, 256>>>(coords, out);
}